// round 5
// baseline (speedup 1.0000x reference)
#include <cuda_runtime.h>
#include <stdint.h>
#include <stddef.h>

// ===========================================================================
// FARGAN vocoder. B=64, T=100, NSUB=4, S=64, HOP=256, IC=512.
// Stage 0: precompute ALL noise (partitionable threefry) -> g_nz
// Stage 1: input MLP for all frames (no recurrence)      -> g_X
// Stage 2: pack/transpose recurrent weights              -> g_wp
// Stage 3: sequential recurrent kernel, 32 CTAs, rows (b, b+32) per CTA.
// ===========================================================================

__device__ float g_A1[6400 * 512];   // concat(features_t, global), row = t*64+b
__device__ float g_H [6400 * 512];   // hidden of input MLP
__device__ float g_X [6400 * 256];   // per-frame excitation
__device__ float4 g_wp[50176];       // packed transposed recurrent weights
__device__ uint2 g_kk[4000];         // per-(step,stream) threefry keys
__device__ float g_nz[18022400];     // 400 steps * 45056 noise values

// per-step noise layout in g_nz (45056 floats):
//   streams q=0..8: q*4096 + b*64 + j   (shape (64,64))
//   stream  q=9   : 36864  + b*128 + j  (shape (64,128))

// packed-weight offsets (float4 units)
#define OFF_FW     0
#define OFF_FWGLU  2048
#define OFF_WIH1   3072
#define OFF_WHH1   9216
#define OFF_GLU1   12288
#define OFF_WIH2   13312
#define OFF_WHH2   19456
#define OFF_GLU2   22528
#define OFF_WIH3   23552
#define OFF_WHH3   29696
#define OFF_GLU3   32768
#define OFF_SKIPD  33792
#define OFF_SKIPG  44032
#define OFF_OUT    48128

// ----------------------------- threefry2x32 --------------------------------
__device__ __forceinline__ uint32_t rotl32(uint32_t v, int s) {
    return (v << s) | (v >> (32 - s));
}
__device__ __forceinline__ uint2 tf2x32(uint2 key, uint2 ctr) {
    uint32_t ks0 = key.x, ks1 = key.y;
    uint32_t ks2 = ks0 ^ ks1 ^ 0x1BD11BDAu;
    uint32_t x0 = ctr.x + ks0, x1 = ctr.y + ks1;
#define TFR(r) { x0 += x1; x1 = rotl32(x1, (r)); x1 ^= x0; }
    TFR(13) TFR(15) TFR(26) TFR(6)   x0 += ks1; x1 += ks2 + 1u;
    TFR(17) TFR(29) TFR(16) TFR(24)  x0 += ks2; x1 += ks0 + 2u;
    TFR(13) TFR(15) TFR(26) TFR(6)   x0 += ks0; x1 += ks1 + 3u;
    TFR(17) TFR(29) TFR(16) TFR(24)  x0 += ks1; x1 += ks2 + 4u;
    TFR(13) TFR(15) TFR(26) TFR(6)   x0 += ks2; x1 += ks0 + 5u;
#undef TFR
    return make_uint2(x0, x1);
}
__device__ __forceinline__ float nzf(uint32_t r) {
    float u = __uint_as_float((r >> 9) | 0x3f800000u) - 1.0f;  // uniform [0,1)
    return (u - 0.5f) * (1.0f / 127.0f);
}
__device__ __forceinline__ float clip1(float v) { return fminf(fmaxf(v, -1.0f), 1.0f); }
__device__ __forceinline__ float sigm(float x) { return 1.0f / (1.0f + expf(-x)); }

// ------------------------- noise precomputation ----------------------------
// foldlike split (jax_threefry_partitionable=True):
//   fkey(step) = tf(key(1)=(0,1), (0, step));  kk[q] = tf(fkey, (0, q))
__global__ void gen_keys() {
    int idx = blockIdx.x * 128 + threadIdx.x;
    if (idx >= 4000) return;
    int step = idx / 10, q = idx % 10;
    uint2 fkey = tf2x32(make_uint2(0u, 1u), make_uint2(0u, (uint32_t)step));
    g_kk[idx] = tf2x32(fkey, make_uint2(0u, (uint32_t)q));
}

// partitionable random_bits (32-bit): element f -> cipher ctr (0, f), bits = x ^ y
__global__ void gen_noise() {
    int rem = blockIdx.x * 256 + threadIdx.x;   // [0, 45056)
    int step = blockIdx.y;
    int q, f;
    if (rem < 36864) { q = rem >> 12; f = rem & 4095; }
    else             { q = 9;         f = rem - 36864; }
    uint2 kk = g_kk[step * 10 + q];
    uint2 c = tf2x32(kk, make_uint2(0u, (uint32_t)f));
    g_nz[(size_t)step * 45056 + rem] = nzf(c.x ^ c.y);
}

// ----------------------------- input MLP -----------------------------------
__global__ void build_a1(const float* __restrict__ feats, const float* __restrict__ gf) {
    int idx = blockIdx.x * blockDim.x + threadIdx.x;
    if (idx >= 6400 * 512) return;
    int row = idx >> 9;          // t*64 + b
    int k = idx & 511;
    int t = row >> 6, b = row & 63;
    float v;
    if (k < 256) v = feats[(b * 256 + k) * 100 + t];   // features[b][k][t]
    else         v = gf[b * 256 + (k - 256)];
    g_A1[idx] = v;
}

template <int ACT>
__device__ __forceinline__ void gemm_body(const float* __restrict__ A,
                                          const float* __restrict__ W,
                                          const float* __restrict__ bias,
                                          float* __restrict__ out, int N, int K) {
    __shared__ float As[64][17];
    __shared__ float Bs[16][65];
    const int bm = blockIdx.x * 64, bn = blockIdx.y * 64;
    const int tx = threadIdx.x & 15, ty = threadIdx.x >> 4;
    float acc[4][4] = {};
    for (int k0 = 0; k0 < K; k0 += 16) {
#pragma unroll
        for (int i = 0; i < 4; i++) {
            int lin = threadIdx.x + i * 256;
            int r = lin >> 4, c = lin & 15;
            As[r][c] = A[(bm + r) * K + k0 + c];
            Bs[c][r] = W[(bn + r) * K + k0 + c];
        }
        __syncthreads();
#pragma unroll
        for (int kk = 0; kk < 16; kk++) {
            float a[4], bb[4];
#pragma unroll
            for (int i = 0; i < 4; i++) a[i] = As[ty * 4 + i][kk];
#pragma unroll
            for (int j = 0; j < 4; j++) bb[j] = Bs[kk][tx * 4 + j];
#pragma unroll
            for (int i = 0; i < 4; i++)
#pragma unroll
                for (int j = 0; j < 4; j++)
                    acc[i][j] = fmaf(a[i], bb[j], acc[i][j]);
        }
        __syncthreads();
    }
#pragma unroll
    for (int i = 0; i < 4; i++) {
        int m = bm + ty * 4 + i;
#pragma unroll
        for (int j = 0; j < 4; j++) {
            int nn = bn + tx * 4 + j;
            float v = acc[i][j] + bias[nn];
            if (ACT) v = tanhf(v);
            out[m * N + nn] = v;
        }
    }
}

__global__ __launch_bounds__(256) void gemm1(const float* __restrict__ W,
                                             const float* __restrict__ b) {
    gemm_body<1>(g_A1, W, b, g_H, 512, 512);
}
__global__ __launch_bounds__(256) void gemm2(const float* __restrict__ W,
                                             const float* __restrict__ b) {
    gemm_body<0>(g_H, W, b, g_X, 256, 512);
}

// ----------------------- weight transpose/pack -----------------------------
// src: N x K row-major. dst[kq*N + n] = float4(src[n][4kq .. 4kq+3])
__global__ void packw(const float* __restrict__ src, int off, int N, int K4) {
    int idx = blockIdx.x * blockDim.x + threadIdx.x;
    if (idx >= N * K4) return;
    int n = idx % N, kq = idx / N;
    const float* s = src + n * (K4 * 4) + 4 * kq;
    g_wp[off + idx] = make_float4(s[0], s[1], s[2], s[3]);
}

// --------------------------- dual-row packed dot ---------------------------
__device__ __forceinline__ float2 dotp(const float4* __restrict__ wp, int n, int N,
                                       const float* __restrict__ x0,
                                       const float* __restrict__ x1, int K4) {
    float a0 = 0.f, a1 = 0.f, b0 = 0.f, b1 = 0.f;
#pragma unroll 4
    for (int kq = 0; kq < K4; kq++) {
        float4 w = wp[kq * N + n];
        float4 xa = *reinterpret_cast<const float4*>(x0 + 4 * kq);
        float4 xb = *reinterpret_cast<const float4*>(x1 + 4 * kq);
        a0 = fmaf(w.x, xa.x, a0); a1 = fmaf(w.y, xa.y, a1);
        a0 = fmaf(w.z, xa.z, a0); a1 = fmaf(w.w, xa.w, a1);
        b0 = fmaf(w.x, xb.x, b0); b1 = fmaf(w.y, xb.y, b1);
        b0 = fmaf(w.z, xb.z, b0); b1 = fmaf(w.w, xb.w, b1);
    }
    return make_float2(a0 + a1, b0 + b1);
}

// --------------------------- recurrent kernel ------------------------------
__global__ __launch_bounds__(192, 1) void fargan_rnn(float* __restrict__ out) {
    const int tid = threadIdx.x;
    const int b0 = blockIdx.x;            // batch rows b0 and b0+32

    __shared__ __align__(16) float sfr0[320], sfr1[320];   // [g1|g2|g3|fw|prevn]
    __shared__ __align__(16) float fwin0[128], fwin1[128]; // [sub_noised | s3]
    __shared__ __align__(16) float tmp0[64], tmp1[64];
    __shared__ __align__(16) float h1a[64], h1b[64], h2a[64], h2b[64], h3a[64], h3b[64];
    __shared__ __align__(16) float prev0[64], prev1[64];
    __shared__ __align__(16) float skb0[128], skb1[128];
    __shared__ __align__(16) float sk20[128], sk21[128];
    __shared__ __align__(16) float nbuf[1408];  // staged noise for this step
    __shared__ float2 ga[192], gb[192];

    if (tid < 64) {
        h1a[tid] = h1b[tid] = h2a[tid] = h2b[tid] = h3a[tid] = h3b[tid] = 0.f;
        prev0[tid] = prev1[tid] = 0.f;
        fwin0[tid] = fwin1[tid] = 0.f;     // s3 seed = 0
    }
    __syncthreads();

#pragma unroll 1
    for (int t = 0; t < 100; t++) {
#pragma unroll 1
        for (int s = 0; s < 4; s++) {
            const int step = t * 4 + s;

            // ---- stage this step's noise into smem (coalesced float4) ----
            // nbuf layout: q<9 -> q*128 + r*64 + j ; q=9 -> 1152 + r*128 + j
            {
                const float* nsrc = g_nz + (size_t)step * 45056;
                for (int c = tid; c < 352; c += 192) {
                    int rho = c >> 4, l = c & 15;
                    int goff, soff;
                    if (rho < 18) {
                        int q = rho >> 1, r = rho & 1;
                        goff = q * 4096 + (b0 + 32 * r) * 64 + l * 4;
                        soff = q * 128 + r * 64 + l * 4;
                    } else {
                        int rho2 = rho - 18;
                        int r = rho2 >> 1, hh = rho2 & 1;
                        goff = 36864 + (b0 + 32 * r) * 128 + hh * 64 + l * 4;
                        soff = 1152 + r * 128 + hh * 64 + l * 4;
                    }
                    *reinterpret_cast<float4*>(nbuf + soff) =
                        *reinterpret_cast<const float4*>(nsrc + goff);
                }
            }
            __syncthreads();

            // ---- phase A: noise sub + prev, shift s3 ----
            if (tid < 64) {
                int j = tid;
                float sx = g_X[(t * 64 + b0) * 256 + s * 64 + j];
                float sy = g_X[(t * 64 + b0 + 32) * 256 + s * 64 + j];
                float olds0 = fwin0[j], olds1 = fwin1[j];
                fwin0[64 + j] = olds0; fwin1[64 + j] = olds1;   // s3 = prev noised sub
                fwin0[j] = clip1(sx + nbuf[j]);                 // stream 0
                fwin1[j] = clip1(sy + nbuf[64 + j]);
                sfr0[256 + j] = clip1(prev0[j] + nbuf[128 + j]); // stream 1
                sfr1[256 + j] = clip1(prev1[j] + nbuf[192 + j]);
            }
            __syncthreads();

            // ---- fw: tanh(concat(sub, s3) @ fw_W.T), then GLU, noise ----
            if (tid < 64) {
                float2 d = dotp(g_wp + OFF_FW, tid, 64, fwin0, fwin1, 32);
                tmp0[tid] = tanhf(d.x); tmp1[tid] = tanhf(d.y);
            }
            __syncthreads();
            if (tid < 64) {
                float2 d = dotp(g_wp + OFF_FWGLU, tid, 64, tmp0, tmp1, 16);
                float gx = tmp0[tid] * sigm(d.x);
                float gy = tmp1[tid] * sigm(d.y);
                sfr0[192 + tid] = clip1(gx + nbuf[256 + tid]);   // stream 2
                sfr1[192 + tid] = clip1(gy + nbuf[320 + tid]);
            }
            __syncthreads();

            // ================= GRU blocks =================
#define GRU_GATES_1(WIHOFF, WHHOFF, HA, HB)                                    \
            {                                                                  \
                float2 gi = dotp(g_wp + (WIHOFF), tid, 192, sfr0 + 192, sfr1 + 192, 32); \
                float2 gh = dotp(g_wp + (WHHOFF), tid, 192, HA, HB, 16);       \
                ga[tid] = gi; gb[tid] = gh;                                    \
            }
#define GRU_GATES_2(WIHOFF, WHHOFF, GOFF, HA, HB)                              \
            {                                                                  \
                float2 p1 = dotp(g_wp + (WIHOFF), tid, 192, sfr0 + (GOFF), sfr1 + (GOFF), 16); \
                float2 p2 = dotp(g_wp + (WIHOFF) + 16 * 192, tid, 192, sfr0 + 256, sfr1 + 256, 16); \
                ga[tid] = make_float2(p1.x + p2.x, p1.y + p2.y);               \
                gb[tid] = dotp(g_wp + (WHHOFF), tid, 192, HA, HB, 16);         \
            }
#define GRU_COMBINE(HA, HB, KH)                                                \
            if (tid < 64) {                                                    \
                int j = tid;                                                   \
                float2 ir = ga[j], hr = gb[j];                                 \
                float2 iz = ga[64 + j], hz = gb[64 + j];                       \
                float2 inn = ga[128 + j], hn = gb[128 + j];                    \
                float hx = HA[j], hy = HB[j];                                  \
                float rx = sigm(ir.x + hr.x), ry = sigm(ir.y + hr.y);          \
                float zx = sigm(iz.x + hz.x), zy = sigm(iz.y + hz.y);          \
                float nx = tanhf(inn.x + rx * hn.x);                           \
                float ny = tanhf(inn.y + ry * hn.y);                           \
                float nhx = (1.0f - zx) * nx + zx * hx;                        \
                float nhy = (1.0f - zy) * ny + zy * hy;                        \
                HA[j] = nhx; HB[j] = nhy;                                      \
                tmp0[j] = clip1(nhx + nbuf[(KH) * 128 + j]);                   \
                tmp1[j] = clip1(nhy + nbuf[(KH) * 128 + 64 + j]);              \
            }
#define GLU_PHASE(GLUOFF, DSTOFF, KG)                                          \
            if (tid < 64) {                                                    \
                float2 d = dotp(g_wp + (GLUOFF), tid, 64, tmp0, tmp1, 16);     \
                float gx = tmp0[tid] * sigm(d.x);                              \
                float gy = tmp1[tid] * sigm(d.y);                              \
                sfr0[(DSTOFF) + tid] = clip1(gx + nbuf[(KG) * 128 + tid]);     \
                sfr1[(DSTOFF) + tid] = clip1(gy + nbuf[(KG) * 128 + 64 + tid]);\
            }

            // GRU1: input = concat(fw, prevn) (contiguous at sfr+192)
            GRU_GATES_1(OFF_WIH1, OFF_WHH1, h1a, h1b);
            __syncthreads();
            GRU_COMBINE(h1a, h1b, 3);
            __syncthreads();
            GLU_PHASE(OFF_GLU1, 0, 4);
            __syncthreads();

            // GRU2: input = concat(g1 @ sfr+0, prevn @ sfr+256)
            GRU_GATES_2(OFF_WIH2, OFF_WHH2, 0, h2a, h2b);
            __syncthreads();
            GRU_COMBINE(h2a, h2b, 5);
            __syncthreads();
            GLU_PHASE(OFF_GLU2, 64, 6);
            __syncthreads();

            // GRU3: input = concat(g2 @ sfr+64, prevn @ sfr+256)
            GRU_GATES_2(OFF_WIH3, OFF_WHH3, 64, h3a, h3b);
            __syncthreads();
            GRU_COMBINE(h3a, h3b, 7);
            __syncthreads();
            GLU_PHASE(OFF_GLU3, 128, 8);
            __syncthreads();

            // ---- skip dense: tanh(sfr @ skipd.T) -> noise (stream 9) -> GLU ----
            if (tid < 128) {
                float2 d = dotp(g_wp + OFF_SKIPD, tid, 128, sfr0, sfr1, 80);
                skb0[tid] = clip1(tanhf(d.x) + nbuf[1152 + tid]);
                skb1[tid] = clip1(tanhf(d.y) + nbuf[1152 + 128 + tid]);
            }
            __syncthreads();
            if (tid < 128) {
                float2 d = dotp(g_wp + OFF_SKIPG, tid, 128, skb0, skb1, 32);
                sk20[tid] = skb0[tid] * sigm(d.x);
                sk21[tid] = skb1[tid] * sigm(d.y);
            }
            __syncthreads();

            // ---- out = tanh(skip @ out_W.T); update prev; write gmem ----
            if (tid < 64) {
                float2 d = dotp(g_wp + OFF_OUT, tid, 64, sk20, sk21, 32);
                float ox = tanhf(d.x), oy = tanhf(d.y);
                int base = t * 256 + s * 64 + tid;
                out[b0 * 25600 + base] = ox;
                out[(b0 + 32) * 25600 + base] = oy;
                prev0[tid] = ox; prev1[tid] = oy;
            }
            __syncthreads();
        }
    }
}

// ------------------------------- launcher ----------------------------------
extern "C" void kernel_launch(void* const* d_in, const int* in_sizes, int n_in,
                              void* d_out, int out_size) {
    const float* features = (const float*)d_in[0];
    const float* gfeat    = (const float*)d_in[1];
    const float* in_W1    = (const float*)d_in[2];
    const float* in_b1    = (const float*)d_in[3];
    const float* in_W2    = (const float*)d_in[4];
    const float* in_b2    = (const float*)d_in[5];
    const float* fw_W     = (const float*)d_in[6];
    const float* fw_glu_W = (const float*)d_in[7];
    const float* g1_Wih   = (const float*)d_in[8];
    const float* g1_Whh   = (const float*)d_in[9];
    const float* glu1_W   = (const float*)d_in[10];
    const float* g2_Wih   = (const float*)d_in[11];
    const float* g2_Whh   = (const float*)d_in[12];
    const float* glu2_W   = (const float*)d_in[13];
    const float* g3_Wih   = (const float*)d_in[14];
    const float* g3_Whh   = (const float*)d_in[15];
    const float* glu3_W   = (const float*)d_in[16];
    const float* skipd_W  = (const float*)d_in[17];
    const float* skipg_W  = (const float*)d_in[18];
    const float* out_W    = (const float*)d_in[19];
    float* out = (float*)d_out;

    // noise precomputation (partitionable threefry)
    gen_keys<<<(4000 + 127) / 128, 128>>>();
    gen_noise<<<dim3(176, 400), 256>>>();

    // input MLP (all frames)
    build_a1<<<12800, 256>>>(features, gfeat);
    gemm1<<<dim3(100, 8), 256>>>(in_W1, in_b1);
    gemm2<<<dim3(100, 4), 256>>>(in_W2, in_b2);

    // pack recurrent weights: (src, off, N, K)
    auto P = [](const float* src, int off, int N, int K) {
        int cnt = N * (K / 4);
        packw<<<(cnt + 255) / 256, 256>>>(src, off, N, K / 4);
    };
    P(fw_W,    OFF_FW,    64, 128);
    P(fw_glu_W,OFF_FWGLU, 64, 64);
    P(g1_Wih,  OFF_WIH1, 192, 128);
    P(g1_Whh,  OFF_WHH1, 192, 64);
    P(glu1_W,  OFF_GLU1,  64, 64);
    P(g2_Wih,  OFF_WIH2, 192, 128);
    P(g2_Whh,  OFF_WHH2, 192, 64);
    P(glu2_W,  OFF_GLU2,  64, 64);
    P(g3_Wih,  OFF_WIH3, 192, 128);
    P(g3_Whh,  OFF_WHH3, 192, 64);
    P(glu3_W,  OFF_GLU3,  64, 64);
    P(skipd_W, OFF_SKIPD,128, 320);
    P(skipg_W, OFF_SKIPG,128, 128);
    P(out_W,   OFF_OUT,   64, 128);

    // sequential recurrent pass
    fargan_rnn<<<32, 192>>>(out);
}

// round 6
// speedup vs baseline: 2.7796x; 2.7796x over previous
#include <cuda_runtime.h>
#include <stdint.h>
#include <stddef.h>

// ===========================================================================
// FARGAN vocoder. B=64, T=100, NSUB=4, S=64, HOP=256, IC=512.
// Stage 0: precompute ALL noise (partitionable threefry) -> g_nz
// Stage 1: input MLP for all frames (no recurrence)      -> g_X
// Stage 2: pack/transpose recurrent weights              -> g_wp
// Stage 3: sequential recurrent kernel, 32 CTAs x 384 thr, rows (b, b+32).
// ===========================================================================

__device__ float g_A1[6400 * 512];
__device__ float g_H [6400 * 512];
__device__ float g_X [6400 * 256];
__device__ float4 g_wp[50176];       // packed transposed recurrent weights
__device__ uint2 g_kk[4000];
__device__ float g_nz[18022400];     // 400 steps * 45056 noise values

// packed-weight offsets (float4 units)
#define OFF_FW     0
#define OFF_FWGLU  2048
#define OFF_WIH1   3072
#define OFF_WHH1   9216
#define OFF_GLU1   12288
#define OFF_WIH2   13312
#define OFF_WHH2   19456
#define OFF_GLU2   22528
#define OFF_WIH3   23552
#define OFF_WHH3   29696
#define OFF_GLU3   32768
#define OFF_SKIPD  33792
#define OFF_SKIPG  44032
#define OFF_OUT    48128

// ----------------------------- threefry2x32 --------------------------------
__device__ __forceinline__ uint32_t rotl32(uint32_t v, int s) {
    return (v << s) | (v >> (32 - s));
}
__device__ __forceinline__ uint2 tf2x32(uint2 key, uint2 ctr) {
    uint32_t ks0 = key.x, ks1 = key.y;
    uint32_t ks2 = ks0 ^ ks1 ^ 0x1BD11BDAu;
    uint32_t x0 = ctr.x + ks0, x1 = ctr.y + ks1;
#define TFR(r) { x0 += x1; x1 = rotl32(x1, (r)); x1 ^= x0; }
    TFR(13) TFR(15) TFR(26) TFR(6)   x0 += ks1; x1 += ks2 + 1u;
    TFR(17) TFR(29) TFR(16) TFR(24)  x0 += ks2; x1 += ks0 + 2u;
    TFR(13) TFR(15) TFR(26) TFR(6)   x0 += ks0; x1 += ks1 + 3u;
    TFR(17) TFR(29) TFR(16) TFR(24)  x0 += ks1; x1 += ks2 + 4u;
    TFR(13) TFR(15) TFR(26) TFR(6)   x0 += ks2; x1 += ks0 + 5u;
#undef TFR
    return make_uint2(x0, x1);
}
__device__ __forceinline__ float nzf(uint32_t r) {
    float u = __uint_as_float((r >> 9) | 0x3f800000u) - 1.0f;
    return (u - 0.5f) * (1.0f / 127.0f);
}
__device__ __forceinline__ float clip1(float v) { return fminf(fmaxf(v, -1.0f), 1.0f); }
__device__ __forceinline__ float sigm(float x) { return 1.0f / (1.0f + expf(-x)); }

// ------------------------- noise precomputation ----------------------------
__global__ void gen_keys() {
    int idx = blockIdx.x * 128 + threadIdx.x;
    if (idx >= 4000) return;
    int step = idx / 10, q = idx % 10;
    uint2 fkey = tf2x32(make_uint2(0u, 1u), make_uint2(0u, (uint32_t)step));
    g_kk[idx] = tf2x32(fkey, make_uint2(0u, (uint32_t)q));
}
__global__ void gen_noise() {
    int rem = blockIdx.x * 256 + threadIdx.x;   // [0, 45056)
    int step = blockIdx.y;
    int q, f;
    if (rem < 36864) { q = rem >> 12; f = rem & 4095; }
    else             { q = 9;         f = rem - 36864; }
    uint2 kk = g_kk[step * 10 + q];
    uint2 c = tf2x32(kk, make_uint2(0u, (uint32_t)f));
    g_nz[(size_t)step * 45056 + rem] = nzf(c.x ^ c.y);
}

// ----------------------------- input MLP -----------------------------------
__global__ void build_a1(const float* __restrict__ feats, const float* __restrict__ gf) {
    int idx = blockIdx.x * blockDim.x + threadIdx.x;
    if (idx >= 6400 * 512) return;
    int row = idx >> 9;
    int k = idx & 511;
    int t = row >> 6, b = row & 63;
    float v;
    if (k < 256) v = feats[(b * 256 + k) * 100 + t];
    else         v = gf[b * 256 + (k - 256)];
    g_A1[idx] = v;
}

template <int ACT>
__device__ __forceinline__ void gemm_body(const float* __restrict__ A,
                                          const float* __restrict__ W,
                                          const float* __restrict__ bias,
                                          float* __restrict__ out, int N, int K) {
    __shared__ float As[64][17];
    __shared__ float Bs[16][65];
    const int bm = blockIdx.x * 64, bn = blockIdx.y * 64;
    const int tx = threadIdx.x & 15, ty = threadIdx.x >> 4;
    float acc[4][4] = {};
    for (int k0 = 0; k0 < K; k0 += 16) {
#pragma unroll
        for (int i = 0; i < 4; i++) {
            int lin = threadIdx.x + i * 256;
            int r = lin >> 4, c = lin & 15;
            As[r][c] = A[(bm + r) * K + k0 + c];
            Bs[c][r] = W[(bn + r) * K + k0 + c];
        }
        __syncthreads();
#pragma unroll
        for (int kk = 0; kk < 16; kk++) {
            float a[4], bb[4];
#pragma unroll
            for (int i = 0; i < 4; i++) a[i] = As[ty * 4 + i][kk];
#pragma unroll
            for (int j = 0; j < 4; j++) bb[j] = Bs[kk][tx * 4 + j];
#pragma unroll
            for (int i = 0; i < 4; i++)
#pragma unroll
                for (int j = 0; j < 4; j++)
                    acc[i][j] = fmaf(a[i], bb[j], acc[i][j]);
        }
        __syncthreads();
    }
#pragma unroll
    for (int i = 0; i < 4; i++) {
        int m = bm + ty * 4 + i;
#pragma unroll
        for (int j = 0; j < 4; j++) {
            int nn = bn + tx * 4 + j;
            float v = acc[i][j] + bias[nn];
            if (ACT) v = tanhf(v);
            out[m * N + nn] = v;
        }
    }
}
__global__ __launch_bounds__(256) void gemm1(const float* __restrict__ W,
                                             const float* __restrict__ b) {
    gemm_body<1>(g_A1, W, b, g_H, 512, 512);
}
__global__ __launch_bounds__(256) void gemm2(const float* __restrict__ W,
                                             const float* __restrict__ b) {
    gemm_body<0>(g_H, W, b, g_X, 256, 512);
}

// ----------------------- weight transpose/pack -----------------------------
__global__ void packw(const float* __restrict__ src, int off, int N, int K4) {
    int idx = blockIdx.x * blockDim.x + threadIdx.x;
    if (idx >= N * K4) return;
    int n = idx % N, kq = idx / N;
    const float* s = src + n * (K4 * 4) + 4 * kq;
    g_wp[off + idx] = make_float4(s[0], s[1], s[2], s[3]);
}

// --------------------------- dual-row packed dot ---------------------------
// wp pre-offset to segment start (units: kq rows of N float4s).
// x  pre-offset (float2 per k, interleaved rows); LEN = #kq (4 k's each).
template <int LEN>
__device__ __forceinline__ float2 dotp2(const float4* __restrict__ wp, int n, int N,
                                        const float2* __restrict__ x) {
    const float4* xv = reinterpret_cast<const float4*>(x);
    float a0 = 0.f, b0 = 0.f, a1 = 0.f, b1 = 0.f;
#pragma unroll
    for (int i = 0; i < LEN; i++) {
        float4 w = wp[i * N + n];
        float4 p = xv[2 * i];
        float4 q = xv[2 * i + 1];
        a0 = fmaf(w.x, p.x, a0); b0 = fmaf(w.x, p.y, b0);
        a1 = fmaf(w.y, p.z, a1); b1 = fmaf(w.y, p.w, b1);
        a0 = fmaf(w.z, q.x, a0); b0 = fmaf(w.z, q.y, b0);
        a1 = fmaf(w.w, q.z, a1); b1 = fmaf(w.w, q.w, b1);
    }
    return make_float2(a0 + a1, b0 + b1);
}

// --------------------------- recurrent kernel ------------------------------
__global__ __launch_bounds__(384, 1) void fargan_rnn(float* __restrict__ out) {
    const int tid = threadIdx.x;
    const int b0 = blockIdx.x;            // batch rows b0 and b0+32

    // interleaved float2 activations: .x = row b0, .y = row b0+32
    __shared__ __align__(16) float2 sfr[320];    // [g1|g2|g3|fw|prevn]
    __shared__ __align__(16) float2 fwin[128];   // [sub_noised | s3]
    __shared__ __align__(16) float2 tmp[64];
    __shared__ __align__(16) float2 h1[64], h2[64], h3[64];
    __shared__ __align__(16) float2 prev[64];
    __shared__ __align__(16) float2 skb[128], sk2[128];
    __shared__ __align__(16) float2 part_a[384], part_b[384];
    __shared__ __align__(16) float nbuf[1408];

    if (tid < 64) {
        h1[tid] = h2[tid] = h3[tid] = make_float2(0.f, 0.f);
        prev[tid] = make_float2(0.f, 0.f);
    }
    if (tid < 128) fwin[tid] = make_float2(0.f, 0.f);
    __syncthreads();

#pragma unroll 1
    for (int t = 0; t < 100; t++) {
#pragma unroll 1
        for (int s = 0; s < 4; s++) {
            const int step = t * 4 + s;

            // ---- stage this step's noise into smem (coalesced float4) ----
            // nbuf: q<9 -> q*128 + r*64 + j ; q=9 -> 1152 + r*128 + j
            if (tid < 352) {
                const float* nsrc = g_nz + (size_t)step * 45056;
                int rho = tid >> 4, l = tid & 15;
                int goff, soff;
                if (rho < 18) {
                    int q = rho >> 1, r = rho & 1;
                    goff = q * 4096 + (b0 + 32 * r) * 64 + l * 4;
                    soff = q * 128 + r * 64 + l * 4;
                } else {
                    int rho2 = rho - 18;
                    int r = rho2 >> 1, hh = rho2 & 1;
                    goff = 36864 + (b0 + 32 * r) * 128 + hh * 64 + l * 4;
                    soff = 1152 + r * 128 + hh * 64 + l * 4;
                }
                *reinterpret_cast<float4*>(nbuf + soff) =
                    *reinterpret_cast<const float4*>(nsrc + goff);
            }
            __syncthreads();

            // ---- phase A: noise sub + prev, shift s3 (128 threads: j,r) ----
            if (tid < 128) {
                int j = tid & 63, r = tid >> 6;
                float* fw_f = reinterpret_cast<float*>(fwin);
                float* sf_f = reinterpret_cast<float*>(sfr);
                const float* pv_f = reinterpret_cast<const float*>(prev);
                float sx = g_X[(t * 64 + b0 + 32 * r) * 256 + s * 64 + j];
                float olds = fw_f[2 * j + r];
                fw_f[2 * (64 + j) + r] = olds;                       // s3
                fw_f[2 * j + r] = clip1(sx + nbuf[r * 64 + j]);      // stream 0
                sf_f[2 * (256 + j) + r] =
                    clip1(pv_f[2 * j + r] + nbuf[128 + r * 64 + j]); // stream 1
            }
            __syncthreads();

            // ---- fw dense: 64 outs, K4=32, 4-way k-split (256 threads) ----
            if (tid < 256) {
                int n = tid & 63, kh = tid >> 6;
                part_a[tid] = dotp2<8>(g_wp + OFF_FW + kh * 8 * 64, n, 64,
                                       fwin + kh * 32);
            }
            __syncthreads();
            if (tid < 64) {
                float2 d = part_a[tid];
                float2 e = part_a[64 + tid], f = part_a[128 + tid], g = part_a[192 + tid];
                tmp[tid] = make_float2(tanhf(d.x + e.x + f.x + g.x),
                                       tanhf(d.y + e.y + f.y + g.y));
            }
            __syncthreads();

            // ---- fw GLU: 64 outs, K4=16, 4-way split ----
            if (tid < 256) {
                int n = tid & 63, kh = tid >> 6;
                part_a[tid] = dotp2<4>(g_wp + OFF_FWGLU + kh * 4 * 64, n, 64,
                                       tmp + kh * 16);
            }
            __syncthreads();
            if (tid < 64) {
                int n = tid;
                float dx = part_a[n].x + part_a[64 + n].x + part_a[128 + n].x + part_a[192 + n].x;
                float dy = part_a[n].y + part_a[64 + n].y + part_a[128 + n].y + part_a[192 + n].y;
                float2 p = tmp[n];
                sfr[192 + n] = make_float2(
                    clip1(p.x * sigm(dx) + nbuf[256 + n]),          // stream 2
                    clip1(p.y * sigm(dy) + nbuf[256 + 64 + n]));
            }
            __syncthreads();

            // ================= GRU blocks =================
            // gates: 384 threads, n = tid%192, kh = tid/192 (2-way k-split)
#define GRU_GATES_1(WIHOFF, WHHOFF, H)                                         \
            {                                                                  \
                int n = tid % 192, kh = tid / 192;                             \
                part_a[tid] = dotp2<16>(g_wp + (WIHOFF) + kh * 16 * 192, n, 192, \
                                        sfr + 192 + kh * 64);                  \
                part_b[tid] = dotp2<8>(g_wp + (WHHOFF) + kh * 8 * 192, n, 192, \
                                       (H) + kh * 32);                         \
            }
#define GRU_GATES_2(WIHOFF, WHHOFF, GOFF, H)                                   \
            {                                                                  \
                int n = tid % 192, kh = tid / 192;                             \
                const float2* actb = kh ? (sfr + 256) : (sfr + (GOFF));        \
                part_a[tid] = dotp2<16>(g_wp + (WIHOFF) + kh * 16 * 192, n, 192, actb); \
                part_b[tid] = dotp2<8>(g_wp + (WHHOFF) + kh * 8 * 192, n, 192, \
                                       (H) + kh * 32);                         \
            }
            // combine: 128 threads (j, r) scalar per row
#define GRU_COMBINE(H, KH)                                                     \
            if (tid < 128) {                                                   \
                int j = tid & 63, r = tid >> 6;                                \
                const float* pa = reinterpret_cast<const float*>(part_a);      \
                const float* pb = reinterpret_cast<const float*>(part_b);      \
                float* hf = reinterpret_cast<float*>(H);                       \
                float* tf = reinterpret_cast<float*>(tmp);                     \
                float gir = pa[2 * j + r]         + pa[2 * (192 + j) + r];     \
                float giz = pa[2 * (64 + j) + r]  + pa[2 * (256 + j) + r];     \
                float gin = pa[2 * (128 + j) + r] + pa[2 * (320 + j) + r];     \
                float ghr = pb[2 * j + r]         + pb[2 * (192 + j) + r];     \
                float ghz = pb[2 * (64 + j) + r]  + pb[2 * (256 + j) + r];     \
                float ghn = pb[2 * (128 + j) + r] + pb[2 * (320 + j) + r];     \
                float hv = hf[2 * j + r];                                      \
                float rr = sigm(gir + ghr);                                    \
                float zz = sigm(giz + ghz);                                    \
                float nn = tanhf(gin + rr * ghn);                              \
                float nh = (1.0f - zz) * nn + zz * hv;                         \
                hf[2 * j + r] = nh;                                            \
                tf[2 * j + r] = clip1(nh + nbuf[(KH) * 128 + r * 64 + j]);     \
            }
            // GLU: 64 outs, K4=16, 4-way split
#define GLU_PHASE(GLUOFF, DSTOFF, KG)                                          \
            if (tid < 256) {                                                   \
                int n = tid & 63, kh = tid >> 6;                               \
                part_a[tid] = dotp2<4>(g_wp + (GLUOFF) + kh * 4 * 64, n, 64,   \
                                       tmp + kh * 16);                         \
            }                                                                  \
            __syncthreads();                                                   \
            if (tid < 64) {                                                    \
                int n = tid;                                                   \
                float dx = part_a[n].x + part_a[64 + n].x + part_a[128 + n].x + part_a[192 + n].x; \
                float dy = part_a[n].y + part_a[64 + n].y + part_a[128 + n].y + part_a[192 + n].y; \
                float2 p = tmp[n];                                             \
                sfr[(DSTOFF) + n] = make_float2(                               \
                    clip1(p.x * sigm(dx) + nbuf[(KG) * 128 + n]),              \
                    clip1(p.y * sigm(dy) + nbuf[(KG) * 128 + 64 + n]));        \
            }

            // GRU1
            GRU_GATES_1(OFF_WIH1, OFF_WHH1, h1);
            __syncthreads();
            GRU_COMBINE(h1, 3);
            __syncthreads();
            GLU_PHASE(OFF_GLU1, 0, 4);
            __syncthreads();

            // GRU2
            GRU_GATES_2(OFF_WIH2, OFF_WHH2, 0, h2);
            __syncthreads();
            GRU_COMBINE(h2, 5);
            __syncthreads();
            GLU_PHASE(OFF_GLU2, 64, 6);
            __syncthreads();

            // GRU3
            GRU_GATES_2(OFF_WIH3, OFF_WHH3, 64, h3);
            __syncthreads();
            GRU_COMBINE(h3, 7);
            __syncthreads();
            GLU_PHASE(OFF_GLU3, 128, 8);
            __syncthreads();

            // ---- skip dense: 128 outs, K4=80 split 27/27/26 (384 threads) ----
            {
                int n = tid & 127, seg = tid >> 7;
                if (seg == 0)
                    part_a[tid] = dotp2<27>(g_wp + OFF_SKIPD, n, 128, sfr);
                else if (seg == 1)
                    part_a[tid] = dotp2<27>(g_wp + OFF_SKIPD + 27 * 128, n, 128, sfr + 108);
                else
                    part_a[tid] = dotp2<26>(g_wp + OFF_SKIPD + 54 * 128, n, 128, sfr + 216);
            }
            __syncthreads();
            if (tid < 128) {
                int n = tid;
                float dx = part_a[n].x + part_a[128 + n].x + part_a[256 + n].x;
                float dy = part_a[n].y + part_a[128 + n].y + part_a[256 + n].y;
                skb[n] = make_float2(clip1(tanhf(dx) + nbuf[1152 + n]),       // stream 9
                                     clip1(tanhf(dy) + nbuf[1152 + 128 + n]));
            }
            __syncthreads();

            // ---- skip GLU: 128 outs, K4=32, 2-way split (256 threads) ----
            if (tid < 256) {
                int n = tid & 127, kh = tid >> 7;
                part_a[tid] = dotp2<16>(g_wp + OFF_SKIPG + kh * 16 * 128, n, 128,
                                        skb + kh * 64);
            }
            __syncthreads();
            if (tid < 128) {
                int n = tid;
                float dx = part_a[n].x + part_a[128 + n].x;
                float dy = part_a[n].y + part_a[128 + n].y;
                float2 p = skb[n];
                sk2[n] = make_float2(p.x * sigm(dx), p.y * sigm(dy));
            }
            __syncthreads();

            // ---- out: 64 outs, K4=32, 4-way split ----
            if (tid < 256) {
                int n = tid & 63, kh = tid >> 6;
                part_a[tid] = dotp2<8>(g_wp + OFF_OUT + kh * 8 * 64, n, 64,
                                       sk2 + kh * 32);
            }
            __syncthreads();
            if (tid < 64) {
                int n = tid;
                float dx = part_a[n].x + part_a[64 + n].x + part_a[128 + n].x + part_a[192 + n].x;
                float dy = part_a[n].y + part_a[64 + n].y + part_a[128 + n].y + part_a[192 + n].y;
                float ox = tanhf(dx), oy = tanhf(dy);
                int base = t * 256 + s * 64 + n;
                out[b0 * 25600 + base] = ox;
                out[(b0 + 32) * 25600 + base] = oy;
                prev[n] = make_float2(ox, oy);
            }
            __syncthreads();
        }
    }
}

// ------------------------------- launcher ----------------------------------
extern "C" void kernel_launch(void* const* d_in, const int* in_sizes, int n_in,
                              void* d_out, int out_size) {
    const float* features = (const float*)d_in[0];
    const float* gfeat    = (const float*)d_in[1];
    const float* in_W1    = (const float*)d_in[2];
    const float* in_b1    = (const float*)d_in[3];
    const float* in_W2    = (const float*)d_in[4];
    const float* in_b2    = (const float*)d_in[5];
    const float* fw_W     = (const float*)d_in[6];
    const float* fw_glu_W = (const float*)d_in[7];
    const float* g1_Wih   = (const float*)d_in[8];
    const float* g1_Whh   = (const float*)d_in[9];
    const float* glu1_W   = (const float*)d_in[10];
    const float* g2_Wih   = (const float*)d_in[11];
    const float* g2_Whh   = (const float*)d_in[12];
    const float* glu2_W   = (const float*)d_in[13];
    const float* g3_Wih   = (const float*)d_in[14];
    const float* g3_Whh   = (const float*)d_in[15];
    const float* glu3_W   = (const float*)d_in[16];
    const float* skipd_W  = (const float*)d_in[17];
    const float* skipg_W  = (const float*)d_in[18];
    const float* out_W    = (const float*)d_in[19];
    float* out = (float*)d_out;

    // noise precomputation (partitionable threefry)
    gen_keys<<<(4000 + 127) / 128, 128>>>();
    gen_noise<<<dim3(176, 400), 256>>>();

    // input MLP (all frames)
    build_a1<<<12800, 256>>>(features, gfeat);
    gemm1<<<dim3(100, 8), 256>>>(in_W1, in_b1);
    gemm2<<<dim3(100, 4), 256>>>(in_W2, in_b2);

    // pack recurrent weights
    auto P = [](const float* src, int off, int N, int K) {
        int cnt = N * (K / 4);
        packw<<<(cnt + 255) / 256, 256>>>(src, off, N, K / 4);
    };
    P(fw_W,    OFF_FW,    64, 128);
    P(fw_glu_W,OFF_FWGLU, 64, 64);
    P(g1_Wih,  OFF_WIH1, 192, 128);
    P(g1_Whh,  OFF_WHH1, 192, 64);
    P(glu1_W,  OFF_GLU1,  64, 64);
    P(g2_Wih,  OFF_WIH2, 192, 128);
    P(g2_Whh,  OFF_WHH2, 192, 64);
    P(glu2_W,  OFF_GLU2,  64, 64);
    P(g3_Wih,  OFF_WIH3, 192, 128);
    P(g3_Whh,  OFF_WHH3, 192, 64);
    P(glu3_W,  OFF_GLU3,  64, 64);
    P(skipd_W, OFF_SKIPD,128, 320);
    P(skipg_W, OFF_SKIPG,128, 128);
    P(out_W,   OFF_OUT,   64, 128);

    // sequential recurrent pass
    fargan_rnn<<<32, 384>>>(out);
}